// round 7
// baseline (speedup 1.0000x reference)
#include <cuda_runtime.h>
#include <mma.h>
#include <cstdint>

using namespace nvcuda;

#define B_ 4096
#define H_ 1024
#define V_ 32000

// -------- scratch (device globals: allocation-free per harness rules) --------
__device__ float g_z [(size_t)B_ * 4096];        // [zf|zi|zc|zo] packed, ld=4096
__device__ float g_wx[(size_t)1024 * 4096];      // [w_ip_f|w_ip_i|w_ip_c|w_ip_o]
__device__ float g_wh[(size_t)1024 * 4096];      // [w_forget|w_input|w_c_dash|w_output]
__device__ float g_wc[(size_t)1024 * 2048];      // [w_forget_c|w_input_c]
__device__ float g_ct[(size_t)B_ * H_];
__device__ float g_ht[(size_t)B_ * H_];

constexpr int BM = 128, BN = 128, BK = 32;
constexpr int APAD = 8, BPAD = 8;
constexpr int A_ROW = BK + APAD;          // 40 floats
constexpr int B_ROW = BN + BPAD;          // 136 floats
constexpr int A_STAGE = BM * A_ROW;       // 5120 floats
constexpr int B_STAGE = BK * B_ROW;       // 4352 floats
constexpr int SMEM_BYTES = 2 * (A_STAGE + B_STAGE) * 4;   // 75776

__device__ __forceinline__ float sigmoidf_(float x) {
    return 1.0f / (1.0f + expf(-x));
}

__device__ __forceinline__ void cp_async16(uint32_t dst, const void* src) {
    asm volatile("cp.async.cg.shared.global [%0], [%1], 16;\n" :: "r"(dst), "l"(src));
}
__device__ __forceinline__ void cp_commit() {
    asm volatile("cp.async.commit_group;\n" ::: "memory");
}
template <int N>
__device__ __forceinline__ void cp_wait() {
    asm volatile("cp.async.wait_group %0;\n" :: "n"(N) : "memory");
}

// -------- weight packing: grid (1024, 10), 256 thr. Each y = one source matrix --------
__global__ void pack_weights(
    const float* uf, const float* ui, const float* uc, const float* uo,
    const float* wf, const float* wi, const float* wc, const float* wo,
    const float* pf, const float* pi)
{
    const int id   = blockIdx.x * 256 + threadIdx.x;   // 0 .. 262143
    const int row  = id >> 8;                          // 0..1023
    const int col4 = (id & 255) * 4;                   // 0..1020
    const int y = blockIdx.y;

    const float* src; float* dst; int ld;
    switch (y) {
        case 0: src = uf; dst = g_wx + 0 * 1024; ld = 4096; break;
        case 1: src = ui; dst = g_wx + 1 * 1024; ld = 4096; break;
        case 2: src = uc; dst = g_wx + 2 * 1024; ld = 4096; break;
        case 3: src = uo; dst = g_wx + 3 * 1024; ld = 4096; break;
        case 4: src = wf; dst = g_wh + 0 * 1024; ld = 4096; break;
        case 5: src = wi; dst = g_wh + 1 * 1024; ld = 4096; break;
        case 6: src = wc; dst = g_wh + 2 * 1024; ld = 4096; break;
        case 7: src = wo; dst = g_wh + 3 * 1024; ld = 4096; break;
        case 8: src = pf; dst = g_wc + 0 * 1024; ld = 2048; break;
        default:src = pi; dst = g_wc + 1 * 1024; ld = 2048; break;
    }
    *(float4*)(dst + (size_t)row * ld + col4) =
        *(const float4*)(src + (size_t)row * 1024 + col4);
}

// ============ pipelined cp.async GEMM (measured 297us/2-pair @grid256) ============
// MODE: 0 = store, 1 = accumulate onto existing C.  A stride fixed = 1024.
template <int MODE, int NPAIR>
__global__ __launch_bounds__(256) void gemm_tf32(
    const float* __restrict__ A0, const float* __restrict__ W0,
    const float* __restrict__ A1, const float* __restrict__ W1,
    float* __restrict__ C, int ldB, int ldC)
{
    extern __shared__ __align__(16) float smem[];
    float* As = smem;                 // [2][BM][A_ROW]
    float* Bs = smem + 2 * A_STAGE;   // [2][BK][B_ROW]

    const int tid    = threadIdx.x;
    const int wid    = tid >> 5;
    const int warp_m = wid & 3;
    const int warp_n = wid >> 2;
    const int bm     = blockIdx.y * BM;
    const int bn     = blockIdx.x * BN;

    const uint32_t sbase = (uint32_t)__cvta_generic_to_shared(smem);

    wmma::fragment<wmma::accumulator, 16, 16, 8, float> acc[2][4];
    #pragma unroll
    for (int i = 0; i < 2; i++)
        #pragma unroll
        for (int j = 0; j < 4; j++) {
            if (MODE == 1) {
                const float* cp = C + (size_t)(bm + warp_m * 32 + i * 16) * ldC
                                    + (bn + warp_n * 64 + j * 16);
                wmma::load_matrix_sync(acc[i][j], cp, ldC, wmma::mem_row_major);
            } else {
                wmma::fill_fragment(acc[i][j], 0.0f);
            }
        }

    const float* Aps[2] = {A0, A1};
    const float* Wps[2] = {W0, W1};
    const int NS = NPAIR * 32;

    const int ar = tid >> 3;             // 0..31
    const int ac = (tid & 7) * 4;        // 0..28
    const int br = tid >> 5;             // 0..7
    const int bc = (tid & 31) * 4;       // 0..124

    auto load_stage = [&](int buf, int s) {
        const int p  = s >> 5;
        const int k0 = (s & 31) * BK;
        const float* __restrict__ A = Aps[p];
        const float* __restrict__ W = Wps[p];
        #pragma unroll
        for (int rr = 0; rr < 4; rr++) {
            uint32_t dst = sbase + (uint32_t)(buf * A_STAGE + (ar + rr * 32) * A_ROW + ac) * 4u;
            cp_async16(dst, A + (size_t)(bm + ar + rr * 32) * 1024 + k0 + ac);
        }
        #pragma unroll
        for (int rr = 0; rr < 4; rr++) {
            uint32_t dst = sbase + (uint32_t)(2 * A_STAGE + buf * B_STAGE + (br + rr * 8) * B_ROW + bc) * 4u;
            cp_async16(dst, W + (size_t)(k0 + br + rr * 8) * ldB + bn + bc);
        }
    };

    load_stage(0, 0);
    cp_commit();

    #pragma unroll 1
    for (int s = 0; s < NS; s++) {
        const int buf = s & 1;
        if (s + 1 < NS) {
            load_stage(buf ^ 1, s + 1);
            cp_commit();
            cp_wait<1>();
        } else {
            cp_wait<0>();
        }
        __syncthreads();

        const float* Ab    = As + buf * A_STAGE;
        const float* Bbase = Bs + buf * B_STAGE;

        #pragma unroll
        for (int kk = 0; kk < BK; kk += 8) {
            wmma::fragment<wmma::matrix_a, 16, 16, 8, wmma::precision::tf32, wmma::row_major> af[2];
            wmma::fragment<wmma::matrix_b, 16, 16, 8, wmma::precision::tf32, wmma::row_major> bf[4];
            #pragma unroll
            for (int i = 0; i < 2; i++) {
                wmma::load_matrix_sync(af[i], Ab + (warp_m * 32 + i * 16) * A_ROW + kk, A_ROW);
                #pragma unroll
                for (int t = 0; t < af[i].num_elements; t++)
                    af[i].x[t] = wmma::__float_to_tf32(af[i].x[t]);
            }
            #pragma unroll
            for (int j = 0; j < 4; j++) {
                wmma::load_matrix_sync(bf[j], Bbase + kk * B_ROW + warp_n * 64 + j * 16, B_ROW);
                #pragma unroll
                for (int t = 0; t < bf[j].num_elements; t++)
                    bf[j].x[t] = wmma::__float_to_tf32(bf[j].x[t]);
            }
            #pragma unroll
            for (int i = 0; i < 2; i++)
                #pragma unroll
                for (int j = 0; j < 4; j++)
                    wmma::mma_sync(acc[i][j], af[i], bf[j], acc[i][j]);
        }
        __syncthreads();
    }

    #pragma unroll
    for (int i = 0; i < 2; i++)
        #pragma unroll
        for (int j = 0; j < 4; j++) {
            float* cp = C + (size_t)(bm + warp_m * 32 + i * 16) * ldC
                          + (bn + warp_n * 64 + j * 16);
            wmma::store_matrix_sync(cp, acc[i][j], ldC, wmma::mem_row_major);
        }
}

// ============ vocab GEMM: measured-good simple body, grid (250, 32) ============
__global__ __launch_bounds__(256) void vocab_kernel(
    const float* __restrict__ A, const float* __restrict__ W,
    float* __restrict__ C, int N)
{
    __shared__ __align__(16) float As[BM][A_ROW];
    __shared__ __align__(16) float Bs[BK][B_ROW];

    const int tid    = threadIdx.x;
    const int wid    = tid >> 5;
    const int warp_m = wid & 3;
    const int warp_n = wid >> 2;
    const int bm     = blockIdx.y * BM;
    const int bn     = blockIdx.x * BN;

    wmma::fragment<wmma::accumulator, 16, 16, 8, float> acc[2][4];
    #pragma unroll
    for (int i = 0; i < 2; i++)
        #pragma unroll
        for (int j = 0; j < 4; j++)
            wmma::fill_fragment(acc[i][j], 0.0f);

    #pragma unroll 1
    for (int k0 = 0; k0 < 1024; k0 += BK) {
        {
            const int r = tid >> 3;
            const int cc = (tid & 7) * 4;
            #pragma unroll
            for (int rr = 0; rr < 4; rr++) {
                float4 v = *(const float4*)(A + (size_t)(bm + r + rr * 32) * 1024 + k0 + cc);
                *(float4*)&As[r + rr * 32][cc] = v;
            }
        }
        {
            const int r = tid >> 5;
            const int cc = (tid & 31) * 4;
            #pragma unroll
            for (int rr = 0; rr < 4; rr++) {
                float4 v = *(const float4*)(W + (size_t)(k0 + r + rr * 8) * N + bn + cc);
                *(float4*)&Bs[r + rr * 8][cc] = v;
            }
        }
        __syncthreads();

        #pragma unroll
        for (int kk = 0; kk < BK; kk += 8) {
            wmma::fragment<wmma::matrix_a, 16, 16, 8, wmma::precision::tf32, wmma::row_major> af[2];
            wmma::fragment<wmma::matrix_b, 16, 16, 8, wmma::precision::tf32, wmma::row_major> bf[4];
            #pragma unroll
            for (int i = 0; i < 2; i++) {
                wmma::load_matrix_sync(af[i], &As[warp_m * 32 + i * 16][kk], A_ROW);
                #pragma unroll
                for (int t = 0; t < af[i].num_elements; t++)
                    af[i].x[t] = wmma::__float_to_tf32(af[i].x[t]);
            }
            #pragma unroll
            for (int j = 0; j < 4; j++) {
                wmma::load_matrix_sync(bf[j], &Bs[kk][warp_n * 64 + j * 16], B_ROW);
                #pragma unroll
                for (int t = 0; t < bf[j].num_elements; t++)
                    bf[j].x[t] = wmma::__float_to_tf32(bf[j].x[t]);
            }
            #pragma unroll
            for (int i = 0; i < 2; i++)
                #pragma unroll
                for (int j = 0; j < 4; j++)
                    wmma::mma_sync(acc[i][j], af[i], bf[j], acc[i][j]);
        }
        __syncthreads();
    }

    #pragma unroll
    for (int i = 0; i < 2; i++)
        #pragma unroll
        for (int j = 0; j < 4; j++) {
            #pragma unroll
            for (int t = 0; t < acc[i][j].num_elements; t++)
                acc[i][j].x[t] = sigmoidf_(acc[i][j].x[t]);
            float* cp = C + (size_t)(bm + warp_m * 32 + i * 16) * N
                          + (bn + warp_n * 64 + j * 16);
            wmma::store_matrix_sync(cp, acc[i][j], N, wmma::mem_row_major);
        }
}

// ======================= elementwise (packed-z layout) =======================
// z layout: [B, 4096] = [zf | zi | zc | zo]
__global__ void lstm_ew1(const float* __restrict__ z, const float* __restrict__ c,
                         float* __restrict__ ct)
{
    int i = blockIdx.x * blockDim.x + threadIdx.x;   // 0 .. B*H-1
    int m = i >> 10, n = i & 1023;
    const float* zr = z + (size_t)m * 4096;
    float Ft = sigmoidf_(zr[n]);
    float It = sigmoidf_(zr[1024 + n]);
    float Cd = tanhf(zr[2048 + n]);
    ct[i] = Ft * c[i] + It * Cd;
}
__global__ void lstm_ew2(const float* __restrict__ z, const float* __restrict__ ct,
                         float* __restrict__ ht)
{
    int i = blockIdx.x * blockDim.x + threadIdx.x;
    int m = i >> 10, n = i & 1023;
    float Ot = sigmoidf_(z[(size_t)m * 4096 + 3072 + n]);
    ht[i] = Ot * tanhf(ct[i]);
}

extern "C" void kernel_launch(void* const* d_in, const int* in_sizes, int n_in,
                              void* d_out, int out_size)
{
    const float* x          = (const float*)d_in[0];
    const float* h          = (const float*)d_in[1];
    const float* c          = (const float*)d_in[2];
    const float* w_forget   = (const float*)d_in[3];
    const float* w_input    = (const float*)d_in[4];
    const float* w_output   = (const float*)d_in[5];
    const float* w_c_dash   = (const float*)d_in[6];
    const float* w_forget_c = (const float*)d_in[7];
    const float* w_input_c  = (const float*)d_in[8];
    const float* w_output_c = (const float*)d_in[9];
    const float* w_op       = (const float*)d_in[10];
    const float* w_ip_f     = (const float*)d_in[11];
    const float* w_ip_i     = (const float*)d_in[12];
    const float* w_ip_o     = (const float*)d_in[13];
    const float* w_ip_c     = (const float*)d_in[14];
    float* out = (float*)d_out;

    cudaFuncSetAttribute((const void*)gemm_tf32<0, 2>, cudaFuncAttributeMaxDynamicSharedMemorySize, SMEM_BYTES);
    cudaFuncSetAttribute((const void*)gemm_tf32<1, 1>, cudaFuncAttributeMaxDynamicSharedMemorySize, SMEM_BYTES);

    float *z, *wx, *wh, *wcp, *ctbuf, *htbuf;
    cudaGetSymbolAddress((void**)&z,  g_z);
    cudaGetSymbolAddress((void**)&wx, g_wx);
    cudaGetSymbolAddress((void**)&wh, g_wh);
    cudaGetSymbolAddress((void**)&wcp, g_wc);
    cudaGetSymbolAddress((void**)&ctbuf, g_ct);
    cudaGetSymbolAddress((void**)&htbuf, g_ht);

    const size_t BV = (size_t)B_ * V_;
    const size_t BH = (size_t)B_ * H_;
    float* ht_out = ((size_t)out_size >= BV + 2 * BH) ? (out + BV)      : htbuf;
    float* ct_out = ((size_t)out_size >= BV + 2 * BH) ? (out + BV + BH) : ctbuf;

    dim3 blk(256);

    // 1) pack weights into wide scratch matrices
    pack_weights<<<dim3(1024, 10), blk>>>(
        w_ip_f, w_ip_i, w_ip_c, w_ip_o,
        w_forget, w_input, w_c_dash, w_output,
        w_forget_c, w_input_c);

    // 2) z = x @ Wx + h @ Wh   [4096 x 4096], one uniform 1024-CTA launch
    gemm_tf32<0, 2><<<dim3(32, 32), blk, SMEM_BYTES>>>(x, wx, h, wh, z, 4096, 4096);

    // 3) z[:, 0:2048] += c @ [w_forget_c | w_input_c]
    gemm_tf32<1, 1><<<dim3(16, 32), blk, SMEM_BYTES>>>(c, wcp, nullptr, nullptr, z, 2048, 4096);

    // 4) Ct
    lstm_ew1<<<(unsigned)(BH / 256), blk>>>(z, c, ct_out);

    // 5) z[:, 3072:4096] += Ct @ w_output_c
    gemm_tf32<1, 1><<<dim3(8, 32), blk, SMEM_BYTES>>>(ct_out, w_output_c, nullptr, nullptr,
                                                      z + 3072, 1024, 4096);

    // 6) Ht
    lstm_ew2<<<(unsigned)(BH / 256), blk>>>(z, ct_out, ht_out);

    // 7) Yt = sigmoid(Ht @ w_op)
    vocab_kernel<<<dim3(250, 32), blk>>>(ht_out, w_op, out, V_);
}

// round 10
// speedup vs baseline: 1.1311x; 1.1311x over previous
#include <cuda_runtime.h>
#include <mma.h>
#include <cstdint>

using namespace nvcuda;

#define B_ 4096
#define H_ 1024
#define V_ 32000

// -------- scratch (device globals: allocation-free per harness rules) --------
__device__ float g_zf[(size_t)B_ * H_];
__device__ float g_zi[(size_t)B_ * H_];
__device__ float g_zc[(size_t)B_ * H_];
__device__ float g_zo[(size_t)B_ * H_];
__device__ float g_ct[(size_t)B_ * H_];
__device__ float g_ht[(size_t)B_ * H_];
__device__ float g_htr[(size_t)B_ * H_];        // tf32-pre-rounded Ht for vocab GEMM
__device__ float g_wop[(size_t)H_ * V_];        // tf32-pre-rounded w_op

constexpr int BM = 128, BN = 128, BK = 32;
constexpr int APAD = 8, BPAD = 8;
constexpr int A_ROW = BK + APAD;          // 40 floats
constexpr int B_ROW = BN + BPAD;          // 136 floats
constexpr int A_STAGE = BM * A_ROW;       // 5120 floats
constexpr int B_STAGE = BK * B_ROW;       // 4352 floats
constexpr int SMEM_BYTES = 2 * (A_STAGE + B_STAGE) * 4;   // 75776

// round_wop grid: H_*V_ floats, 4 per thread, 256 threads/block = 32000 blocks exactly.
constexpr unsigned ROUND_WOP_BLOCKS = (unsigned)((size_t)H_ * V_ / (4 * 256));
static_assert((size_t)ROUND_WOP_BLOCKS * 4 * 256 == (size_t)H_ * V_, "round_wop grid must cover exactly");

__device__ __forceinline__ float sigmoidf_(float x) {
    return 1.0f / (1.0f + expf(-x));
}

__device__ __forceinline__ void cp_async16(uint32_t dst, const void* src) {
    asm volatile("cp.async.cg.shared.global [%0], [%1], 16;\n" :: "r"(dst), "l"(src));
}
__device__ __forceinline__ void cp_commit() {
    asm volatile("cp.async.commit_group;\n" ::: "memory");
}
template <int N>
__device__ __forceinline__ void cp_wait() {
    asm volatile("cp.async.wait_group %0;\n" :: "n"(N) : "memory");
}

// ============ pipelined cp.async GEMM — R6-measured config (gates/peephole) ============
// MODE: 0 = store, 1 = accumulate onto existing C.
template <int MODE, int NPAIR>
__global__ __launch_bounds__(256) void gemm_tf32(
    const float* __restrict__ A0, const float* __restrict__ W0,
    const float* __restrict__ A1, const float* __restrict__ W1,
    const float* __restrict__ A2, const float* __restrict__ W2,
    float* __restrict__ C, int N)
{
    extern __shared__ __align__(16) float smem[];
    float* As = smem;                 // [2][BM][A_ROW]
    float* Bs = smem + 2 * A_STAGE;   // [2][BK][B_ROW]

    const int tid    = threadIdx.x;
    const int wid    = tid >> 5;
    const int warp_m = wid & 3;
    const int warp_n = wid >> 2;
    const int bm     = blockIdx.y * BM;
    const int bn     = blockIdx.x * BN;

    const uint32_t sbase = (uint32_t)__cvta_generic_to_shared(smem);

    wmma::fragment<wmma::accumulator, 16, 16, 8, float> acc[2][4];
    #pragma unroll
    for (int i = 0; i < 2; i++)
        #pragma unroll
        for (int j = 0; j < 4; j++) {
            if (MODE == 1) {
                const float* cp = C + (size_t)(bm + warp_m * 32 + i * 16) * N
                                    + (bn + warp_n * 64 + j * 16);
                wmma::load_matrix_sync(acc[i][j], cp, N, wmma::mem_row_major);
            } else {
                wmma::fill_fragment(acc[i][j], 0.0f);
            }
        }

    const float* Aps[3] = {A0, A1, A2};
    const float* Wps[3] = {W0, W1, W2};
    const int NS = NPAIR * 32;

    const int ar = tid >> 3;             // 0..31
    const int ac = (tid & 7) * 4;        // 0..28
    const int br = tid >> 5;             // 0..7
    const int bc = (tid & 31) * 4;       // 0..124

    auto load_stage = [&](int buf, int s) {
        const int p  = s >> 5;
        const int k0 = (s & 31) * BK;
        const float* __restrict__ A = Aps[p];
        const float* __restrict__ W = Wps[p];
        #pragma unroll
        for (int rr = 0; rr < 4; rr++) {
            uint32_t dst = sbase + (uint32_t)(buf * A_STAGE + (ar + rr * 32) * A_ROW + ac) * 4u;
            cp_async16(dst, A + (size_t)(bm + ar + rr * 32) * 1024 + k0 + ac);
        }
        #pragma unroll
        for (int rr = 0; rr < 4; rr++) {
            uint32_t dst = sbase + (uint32_t)(2 * A_STAGE + buf * B_STAGE + (br + rr * 8) * B_ROW + bc) * 4u;
            cp_async16(dst, W + (size_t)(k0 + br + rr * 8) * N + bn + bc);
        }
    };

    load_stage(0, 0);
    cp_commit();

    #pragma unroll 1
    for (int s = 0; s < NS; s++) {
        const int buf = s & 1;
        if (s + 1 < NS) {
            load_stage(buf ^ 1, s + 1);
            cp_commit();
            cp_wait<1>();
        } else {
            cp_wait<0>();
        }
        __syncthreads();

        const float* Ab    = As + buf * A_STAGE;
        const float* Bbase = Bs + buf * B_STAGE;

        #pragma unroll
        for (int kk = 0; kk < BK; kk += 8) {
            wmma::fragment<wmma::matrix_a, 16, 16, 8, wmma::precision::tf32, wmma::row_major> af[2];
            wmma::fragment<wmma::matrix_b, 16, 16, 8, wmma::precision::tf32, wmma::row_major> bf[4];
            #pragma unroll
            for (int i = 0; i < 2; i++) {
                wmma::load_matrix_sync(af[i], Ab + (warp_m * 32 + i * 16) * A_ROW + kk, A_ROW);
                #pragma unroll
                for (int t = 0; t < af[i].num_elements; t++)
                    af[i].x[t] = wmma::__float_to_tf32(af[i].x[t]);
            }
            #pragma unroll
            for (int j = 0; j < 4; j++) {
                wmma::load_matrix_sync(bf[j], Bbase + kk * B_ROW + warp_n * 64 + j * 16, B_ROW);
                #pragma unroll
                for (int t = 0; t < bf[j].num_elements; t++)
                    bf[j].x[t] = wmma::__float_to_tf32(bf[j].x[t]);
            }
            #pragma unroll
            for (int i = 0; i < 2; i++)
                #pragma unroll
                for (int j = 0; j < 4; j++)
                    wmma::mma_sync(acc[i][j], af[i], bf[j], acc[i][j]);
        }
        __syncthreads();
    }

    #pragma unroll
    for (int i = 0; i < 2; i++)
        #pragma unroll
        for (int j = 0; j < 4; j++) {
            float* cp = C + (size_t)(bm + warp_m * 32 + i * 16) * N
                          + (bn + warp_n * 64 + j * 16);
            wmma::store_matrix_sync(cp, acc[i][j], N, wmma::mem_row_major);
        }
}

// -------- pre-round w_op to tf32 (same cvt as in-loop conversion => identical bits) --------
__global__ void round_wop(const float* __restrict__ src, float* __restrict__ dst)
{
    size_t i = ((size_t)blockIdx.x * 256 + threadIdx.x) * 4;   // float4 granularity
    float4 v = *(const float4*)(src + i);
    v.x = wmma::__float_to_tf32(v.x);
    v.y = wmma::__float_to_tf32(v.y);
    v.z = wmma::__float_to_tf32(v.z);
    v.w = wmma::__float_to_tf32(v.w);
    *(float4*)(dst + i) = v;
}

// ============ vocab GEMM: simple body (measured 3.3ms), conversions hoisted out ============
// A (g_htr) and W (g_wop) are pre-rounded tf32 => no in-loop cvt needed; identical bits.
__global__ __launch_bounds__(256) void vocab_kernel(
    const float* __restrict__ A, const float* __restrict__ W,
    float* __restrict__ C, int N)
{
    __shared__ __align__(16) float As[BM][A_ROW];
    __shared__ __align__(16) float Bs[BK][B_ROW];

    const int tid    = threadIdx.x;
    const int wid    = tid >> 5;
    const int warp_m = wid & 3;
    const int warp_n = wid >> 2;
    const int bm     = blockIdx.y * BM;
    const int bn     = blockIdx.x * BN;

    wmma::fragment<wmma::accumulator, 16, 16, 8, float> acc[2][4];
    #pragma unroll
    for (int i = 0; i < 2; i++)
        #pragma unroll
        for (int j = 0; j < 4; j++)
            wmma::fill_fragment(acc[i][j], 0.0f);

    #pragma unroll 1
    for (int k0 = 0; k0 < 1024; k0 += BK) {
        {
            const int r = tid >> 3;
            const int cc = (tid & 7) * 4;
            #pragma unroll
            for (int rr = 0; rr < 4; rr++) {
                float4 v = *(const float4*)(A + (size_t)(bm + r + rr * 32) * 1024 + k0 + cc);
                *(float4*)&As[r + rr * 32][cc] = v;
            }
        }
        {
            const int r = tid >> 5;
            const int cc = (tid & 31) * 4;
            #pragma unroll
            for (int rr = 0; rr < 4; rr++) {
                float4 v = *(const float4*)(W + (size_t)(k0 + r + rr * 8) * N + bn + cc);
                *(float4*)&Bs[r + rr * 8][cc] = v;
            }
        }
        __syncthreads();

        #pragma unroll
        for (int kk = 0; kk < BK; kk += 8) {
            wmma::fragment<wmma::matrix_a, 16, 16, 8, wmma::precision::tf32, wmma::row_major> af[2];
            wmma::fragment<wmma::matrix_b, 16, 16, 8, wmma::precision::tf32, wmma::row_major> bf[4];
            #pragma unroll
            for (int i = 0; i < 2; i++)
                wmma::load_matrix_sync(af[i], &As[warp_m * 32 + i * 16][kk], A_ROW);
            #pragma unroll
            for (int j = 0; j < 4; j++)
                wmma::load_matrix_sync(bf[j], &Bs[kk][warp_n * 64 + j * 16], B_ROW);
            #pragma unroll
            for (int i = 0; i < 2; i++)
                #pragma unroll
                for (int j = 0; j < 4; j++)
                    wmma::mma_sync(acc[i][j], af[i], bf[j], acc[i][j]);
        }
        __syncthreads();
    }

    #pragma unroll
    for (int i = 0; i < 2; i++)
        #pragma unroll
        for (int j = 0; j < 4; j++) {
            #pragma unroll
            for (int t = 0; t < acc[i][j].num_elements; t++)
                acc[i][j].x[t] = sigmoidf_(acc[i][j].x[t]);
            float* cp = C + (size_t)(bm + warp_m * 32 + i * 16) * N
                          + (bn + warp_n * 64 + j * 16);
            wmma::store_matrix_sync(cp, acc[i][j], N, wmma::mem_row_major);
        }
}

// ======================= elementwise =======================
__global__ void lstm_ew1(const float* __restrict__ zf, const float* __restrict__ zi,
                         const float* __restrict__ zc, const float* __restrict__ c,
                         float* __restrict__ ct, int n)
{
    int i = blockIdx.x * blockDim.x + threadIdx.x;
    if (i < n)
        ct[i] = sigmoidf_(zf[i]) * c[i] + sigmoidf_(zi[i]) * tanhf(zc[i]);
}
// Ht (exact) -> ht; Ht (tf32-rounded) -> htr for the vocab GEMM
__global__ void lstm_ew2(const float* __restrict__ zo, const float* __restrict__ ct,
                         float* __restrict__ ht, float* __restrict__ htr, int n)
{
    int i = blockIdx.x * blockDim.x + threadIdx.x;
    if (i < n) {
        float v = sigmoidf_(zo[i]) * tanhf(ct[i]);
        ht[i]  = v;
        htr[i] = wmma::__float_to_tf32(v);
    }
}

extern "C" void kernel_launch(void* const* d_in, const int* in_sizes, int n_in,
                              void* d_out, int out_size)
{
    const float* x          = (const float*)d_in[0];
    const float* h          = (const float*)d_in[1];
    const float* c          = (const float*)d_in[2];
    const float* w_forget   = (const float*)d_in[3];
    const float* w_input    = (const float*)d_in[4];
    const float* w_output   = (const float*)d_in[5];
    const float* w_c_dash   = (const float*)d_in[6];
    const float* w_forget_c = (const float*)d_in[7];
    const float* w_input_c  = (const float*)d_in[8];
    const float* w_output_c = (const float*)d_in[9];
    const float* w_op       = (const float*)d_in[10];
    const float* w_ip_f     = (const float*)d_in[11];
    const float* w_ip_i     = (const float*)d_in[12];
    const float* w_ip_o     = (const float*)d_in[13];
    const float* w_ip_c     = (const float*)d_in[14];
    float* out = (float*)d_out;

    cudaFuncSetAttribute((const void*)gemm_tf32<0, 3>, cudaFuncAttributeMaxDynamicSharedMemorySize, SMEM_BYTES);
    cudaFuncSetAttribute((const void*)gemm_tf32<0, 2>, cudaFuncAttributeMaxDynamicSharedMemorySize, SMEM_BYTES);
    cudaFuncSetAttribute((const void*)gemm_tf32<1, 1>, cudaFuncAttributeMaxDynamicSharedMemorySize, SMEM_BYTES);

    float *zf, *zi, *zc, *zo, *ctbuf, *htbuf, *htr, *wop;
    cudaGetSymbolAddress((void**)&zf, g_zf);
    cudaGetSymbolAddress((void**)&zi, g_zi);
    cudaGetSymbolAddress((void**)&zc, g_zc);
    cudaGetSymbolAddress((void**)&zo, g_zo);
    cudaGetSymbolAddress((void**)&ctbuf, g_ct);
    cudaGetSymbolAddress((void**)&htbuf, g_ht);
    cudaGetSymbolAddress((void**)&htr, g_htr);
    cudaGetSymbolAddress((void**)&wop, g_wop);

    const size_t BV = (size_t)B_ * V_;
    const size_t BH = (size_t)B_ * H_;
    float* ht_out = ((size_t)out_size >= BV + 2 * BH) ? (out + BV)      : htbuf;
    float* ct_out = ((size_t)out_size >= BV + 2 * BH) ? (out + BV + BH) : ctbuf;

    dim3 blk(256);
    dim3 g_h(8, 32);

    // Pre-round w_op to tf32: exactly H_*V_ floats, 4/thread, 256 thr/blk = 32000 blocks.
    round_wop<<<ROUND_WOP_BLOCKS, blk>>>(w_op, wop);

    // Gate pre-activations — 4 separate pipelined launches (R6-measured config)
    gemm_tf32<0, 3><<<g_h, blk, SMEM_BYTES>>>(x, w_ip_f, h, w_forget, c, w_forget_c, zf, 1024);
    gemm_tf32<0, 3><<<g_h, blk, SMEM_BYTES>>>(x, w_ip_i, h, w_input,  c, w_input_c,  zi, 1024);
    gemm_tf32<0, 2><<<g_h, blk, SMEM_BYTES>>>(x, w_ip_c, h, w_c_dash, nullptr, nullptr, zc, 1024);
    gemm_tf32<0, 2><<<g_h, blk, SMEM_BYTES>>>(x, w_ip_o, h, w_output, nullptr, nullptr, zo, 1024);

    lstm_ew1<<<(unsigned)(BH / 256), blk>>>(zf, zi, zc, c, ct_out, (int)BH);

    // zo += Ct @ w_output_c
    gemm_tf32<1, 1><<<g_h, blk, SMEM_BYTES>>>(ct_out, w_output_c, nullptr, nullptr, nullptr, nullptr,
                                              zo, 1024);

    lstm_ew2<<<(unsigned)(BH / 256), blk>>>(zo, ct_out, ht_out, htr, (int)BH);

    // Yt = sigmoid(Htr @ Wop_rounded) — conversion-free inner loop
    vocab_kernel<<<dim3(250, 32), blk>>>(htr, wop, out, V_);
}

// round 11
// speedup vs baseline: 1.3461x; 1.1901x over previous
#include <cuda_runtime.h>
#include <mma.h>
#include <cstdint>

using namespace nvcuda;

#define B_ 4096
#define H_ 1024
#define V_ 32000

// -------- scratch (device globals: allocation-free per harness rules) --------
__device__ float g_zf[(size_t)B_ * H_];
__device__ float g_zi[(size_t)B_ * H_];
__device__ float g_zc[(size_t)B_ * H_];
__device__ float g_zo[(size_t)B_ * H_];
__device__ float g_ct[(size_t)B_ * H_];
__device__ float g_ht[(size_t)B_ * H_];
__device__ float g_htr[(size_t)B_ * H_];        // tf32-pre-rounded Ht for vocab GEMM
__device__ float g_wop[(size_t)H_ * V_];        // tf32-pre-rounded w_op

constexpr int BM = 128, BN = 128, BK = 32;
constexpr int APAD = 8, BPAD = 8;
constexpr int A_ROW = BK + APAD;          // 40 floats
constexpr int B_ROW = BN + BPAD;          // 136 floats
constexpr int A_STAGE = BM * A_ROW;       // 5120 floats
constexpr int B_STAGE = BK * B_ROW;       // 4352 floats
constexpr int SMEM_BYTES = 2 * (A_STAGE + B_STAGE) * 4;   // 75776

// round_wop grid: H_*V_ floats, 4 per thread, 256 threads/block = 32000 blocks exactly.
constexpr unsigned ROUND_WOP_BLOCKS = (unsigned)((size_t)H_ * V_ / (4 * 256));
static_assert((size_t)ROUND_WOP_BLOCKS * 4 * 256 == (size_t)H_ * V_, "round_wop grid must cover exactly");

__device__ __forceinline__ float sigmoidf_(float x) {
    return 1.0f / (1.0f + expf(-x));
}

__device__ __forceinline__ void cp_async16(uint32_t dst, const void* src) {
    asm volatile("cp.async.cg.shared.global [%0], [%1], 16;\n" :: "r"(dst), "l"(src));
}
__device__ __forceinline__ void cp_commit() {
    asm volatile("cp.async.commit_group;\n" ::: "memory");
}
template <int N>
__device__ __forceinline__ void cp_wait() {
    asm volatile("cp.async.wait_group %0;\n" :: "n"(N) : "memory");
}

// ============ pipelined cp.async GEMM — R6-measured config (gates/peephole) ============
// MODE: 0 = store, 1 = accumulate onto existing C.
template <int MODE, int NPAIR>
__global__ __launch_bounds__(256) void gemm_tf32(
    const float* __restrict__ A0, const float* __restrict__ W0,
    const float* __restrict__ A1, const float* __restrict__ W1,
    const float* __restrict__ A2, const float* __restrict__ W2,
    float* __restrict__ C, int N)
{
    extern __shared__ __align__(16) float smem[];
    float* As = smem;                 // [2][BM][A_ROW]
    float* Bs = smem + 2 * A_STAGE;   // [2][BK][B_ROW]

    const int tid    = threadIdx.x;
    const int wid    = tid >> 5;
    const int warp_m = wid & 3;
    const int warp_n = wid >> 2;
    const int bm     = blockIdx.y * BM;
    const int bn     = blockIdx.x * BN;

    const uint32_t sbase = (uint32_t)__cvta_generic_to_shared(smem);

    wmma::fragment<wmma::accumulator, 16, 16, 8, float> acc[2][4];
    #pragma unroll
    for (int i = 0; i < 2; i++)
        #pragma unroll
        for (int j = 0; j < 4; j++) {
            if (MODE == 1) {
                const float* cp = C + (size_t)(bm + warp_m * 32 + i * 16) * N
                                    + (bn + warp_n * 64 + j * 16);
                wmma::load_matrix_sync(acc[i][j], cp, N, wmma::mem_row_major);
            } else {
                wmma::fill_fragment(acc[i][j], 0.0f);
            }
        }

    const float* Aps[3] = {A0, A1, A2};
    const float* Wps[3] = {W0, W1, W2};
    const int NS = NPAIR * 32;

    const int ar = tid >> 3;             // 0..31
    const int ac = (tid & 7) * 4;        // 0..28
    const int br = tid >> 5;             // 0..7
    const int bc = (tid & 31) * 4;       // 0..124

    auto load_stage = [&](int buf, int s) {
        const int p  = s >> 5;
        const int k0 = (s & 31) * BK;
        const float* __restrict__ A = Aps[p];
        const float* __restrict__ W = Wps[p];
        #pragma unroll
        for (int rr = 0; rr < 4; rr++) {
            uint32_t dst = sbase + (uint32_t)(buf * A_STAGE + (ar + rr * 32) * A_ROW + ac) * 4u;
            cp_async16(dst, A + (size_t)(bm + ar + rr * 32) * 1024 + k0 + ac);
        }
        #pragma unroll
        for (int rr = 0; rr < 4; rr++) {
            uint32_t dst = sbase + (uint32_t)(2 * A_STAGE + buf * B_STAGE + (br + rr * 8) * B_ROW + bc) * 4u;
            cp_async16(dst, W + (size_t)(k0 + br + rr * 8) * N + bn + bc);
        }
    };

    load_stage(0, 0);
    cp_commit();

    #pragma unroll 1
    for (int s = 0; s < NS; s++) {
        const int buf = s & 1;
        if (s + 1 < NS) {
            load_stage(buf ^ 1, s + 1);
            cp_commit();
            cp_wait<1>();
        } else {
            cp_wait<0>();
        }
        __syncthreads();

        const float* Ab    = As + buf * A_STAGE;
        const float* Bbase = Bs + buf * B_STAGE;

        #pragma unroll
        for (int kk = 0; kk < BK; kk += 8) {
            wmma::fragment<wmma::matrix_a, 16, 16, 8, wmma::precision::tf32, wmma::row_major> af[2];
            wmma::fragment<wmma::matrix_b, 16, 16, 8, wmma::precision::tf32, wmma::row_major> bf[4];
            #pragma unroll
            for (int i = 0; i < 2; i++) {
                wmma::load_matrix_sync(af[i], Ab + (warp_m * 32 + i * 16) * A_ROW + kk, A_ROW);
                #pragma unroll
                for (int t = 0; t < af[i].num_elements; t++)
                    af[i].x[t] = wmma::__float_to_tf32(af[i].x[t]);
            }
            #pragma unroll
            for (int j = 0; j < 4; j++) {
                wmma::load_matrix_sync(bf[j], Bbase + kk * B_ROW + warp_n * 64 + j * 16, B_ROW);
                #pragma unroll
                for (int t = 0; t < bf[j].num_elements; t++)
                    bf[j].x[t] = wmma::__float_to_tf32(bf[j].x[t]);
            }
            #pragma unroll
            for (int i = 0; i < 2; i++)
                #pragma unroll
                for (int j = 0; j < 4; j++)
                    wmma::mma_sync(acc[i][j], af[i], bf[j], acc[i][j]);
        }
        __syncthreads();
    }

    #pragma unroll
    for (int i = 0; i < 2; i++)
        #pragma unroll
        for (int j = 0; j < 4; j++) {
            float* cp = C + (size_t)(bm + warp_m * 32 + i * 16) * N
                          + (bn + warp_n * 64 + j * 16);
            wmma::store_matrix_sync(cp, acc[i][j], N, wmma::mem_row_major);
        }
}

// -------- pre-round w_op to tf32 (same cvt as in-loop conversion => identical bits) --------
__global__ void round_wop(const float* __restrict__ src, float* __restrict__ dst)
{
    size_t i = ((size_t)blockIdx.x * 256 + threadIdx.x) * 4;   // float4 granularity
    float4 v = *(const float4*)(src + i);
    v.x = wmma::__float_to_tf32(v.x);
    v.y = wmma::__float_to_tf32(v.y);
    v.z = wmma::__float_to_tf32(v.z);
    v.w = wmma::__float_to_tf32(v.w);
    *(float4*)(dst + i) = v;
}

// ============ vocab GEMM: conversion-free body + FORCED 2 CTAs/SM ============
// A (g_htr) and W (g_wop) pre-rounded tf32 => no in-loop cvt; regs fit 128 cap.
// __launch_bounds__(256, 2): 2 CTAs/SM -> 4 warps/SMSP -> hide HMMA/LDS latency.
__global__ __launch_bounds__(256, 2) void vocab_kernel(
    const float* __restrict__ A, const float* __restrict__ W,
    float* __restrict__ C, int N)
{
    __shared__ __align__(16) float As[BM][A_ROW];
    __shared__ __align__(16) float Bs[BK][B_ROW];

    const int tid    = threadIdx.x;
    const int wid    = tid >> 5;
    const int warp_m = wid & 3;
    const int warp_n = wid >> 2;
    const int bm     = blockIdx.y * BM;
    const int bn     = blockIdx.x * BN;

    wmma::fragment<wmma::accumulator, 16, 16, 8, float> acc[2][4];
    #pragma unroll
    for (int i = 0; i < 2; i++)
        #pragma unroll
        for (int j = 0; j < 4; j++)
            wmma::fill_fragment(acc[i][j], 0.0f);

    #pragma unroll 1
    for (int k0 = 0; k0 < 1024; k0 += BK) {
        {
            const int r = tid >> 3;
            const int cc = (tid & 7) * 4;
            #pragma unroll
            for (int rr = 0; rr < 4; rr++) {
                float4 v = *(const float4*)(A + (size_t)(bm + r + rr * 32) * 1024 + k0 + cc);
                *(float4*)&As[r + rr * 32][cc] = v;
            }
        }
        {
            const int r = tid >> 5;
            const int cc = (tid & 31) * 4;
            #pragma unroll
            for (int rr = 0; rr < 4; rr++) {
                float4 v = *(const float4*)(W + (size_t)(k0 + r + rr * 8) * N + bn + cc);
                *(float4*)&Bs[r + rr * 8][cc] = v;
            }
        }
        __syncthreads();

        #pragma unroll
        for (int kk = 0; kk < BK; kk += 8) {
            wmma::fragment<wmma::matrix_a, 16, 16, 8, wmma::precision::tf32, wmma::row_major> af[2];
            wmma::fragment<wmma::matrix_b, 16, 16, 8, wmma::precision::tf32, wmma::row_major> bf[4];
            #pragma unroll
            for (int i = 0; i < 2; i++)
                wmma::load_matrix_sync(af[i], &As[warp_m * 32 + i * 16][kk], A_ROW);
            #pragma unroll
            for (int j = 0; j < 4; j++)
                wmma::load_matrix_sync(bf[j], &Bs[kk][warp_n * 64 + j * 16], B_ROW);
            #pragma unroll
            for (int i = 0; i < 2; i++)
                #pragma unroll
                for (int j = 0; j < 4; j++)
                    wmma::mma_sync(acc[i][j], af[i], bf[j], acc[i][j]);
        }
        __syncthreads();
    }

    #pragma unroll
    for (int i = 0; i < 2; i++)
        #pragma unroll
        for (int j = 0; j < 4; j++) {
            #pragma unroll
            for (int t = 0; t < acc[i][j].num_elements; t++)
                acc[i][j].x[t] = sigmoidf_(acc[i][j].x[t]);
            float* cp = C + (size_t)(bm + warp_m * 32 + i * 16) * N
                          + (bn + warp_n * 64 + j * 16);
            wmma::store_matrix_sync(cp, acc[i][j], N, wmma::mem_row_major);
        }
}

// ======================= elementwise =======================
__global__ void lstm_ew1(const float* __restrict__ zf, const float* __restrict__ zi,
                         const float* __restrict__ zc, const float* __restrict__ c,
                         float* __restrict__ ct, int n)
{
    int i = blockIdx.x * blockDim.x + threadIdx.x;
    if (i < n)
        ct[i] = sigmoidf_(zf[i]) * c[i] + sigmoidf_(zi[i]) * tanhf(zc[i]);
}
// Ht (exact) -> ht; Ht (tf32-rounded) -> htr for the vocab GEMM
__global__ void lstm_ew2(const float* __restrict__ zo, const float* __restrict__ ct,
                         float* __restrict__ ht, float* __restrict__ htr, int n)
{
    int i = blockIdx.x * blockDim.x + threadIdx.x;
    if (i < n) {
        float v = sigmoidf_(zo[i]) * tanhf(ct[i]);
        ht[i]  = v;
        htr[i] = wmma::__float_to_tf32(v);
    }
}

extern "C" void kernel_launch(void* const* d_in, const int* in_sizes, int n_in,
                              void* d_out, int out_size)
{
    const float* x          = (const float*)d_in[0];
    const float* h          = (const float*)d_in[1];
    const float* c          = (const float*)d_in[2];
    const float* w_forget   = (const float*)d_in[3];
    const float* w_input    = (const float*)d_in[4];
    const float* w_output   = (const float*)d_in[5];
    const float* w_c_dash   = (const float*)d_in[6];
    const float* w_forget_c = (const float*)d_in[7];
    const float* w_input_c  = (const float*)d_in[8];
    const float* w_output_c = (const float*)d_in[9];
    const float* w_op       = (const float*)d_in[10];
    const float* w_ip_f     = (const float*)d_in[11];
    const float* w_ip_i     = (const float*)d_in[12];
    const float* w_ip_o     = (const float*)d_in[13];
    const float* w_ip_c     = (const float*)d_in[14];
    float* out = (float*)d_out;

    cudaFuncSetAttribute((const void*)gemm_tf32<0, 3>, cudaFuncAttributeMaxDynamicSharedMemorySize, SMEM_BYTES);
    cudaFuncSetAttribute((const void*)gemm_tf32<0, 2>, cudaFuncAttributeMaxDynamicSharedMemorySize, SMEM_BYTES);
    cudaFuncSetAttribute((const void*)gemm_tf32<1, 1>, cudaFuncAttributeMaxDynamicSharedMemorySize, SMEM_BYTES);

    float *zf, *zi, *zc, *zo, *ctbuf, *htbuf, *htr, *wop;
    cudaGetSymbolAddress((void**)&zf, g_zf);
    cudaGetSymbolAddress((void**)&zi, g_zi);
    cudaGetSymbolAddress((void**)&zc, g_zc);
    cudaGetSymbolAddress((void**)&zo, g_zo);
    cudaGetSymbolAddress((void**)&ctbuf, g_ct);
    cudaGetSymbolAddress((void**)&htbuf, g_ht);
    cudaGetSymbolAddress((void**)&htr, g_htr);
    cudaGetSymbolAddress((void**)&wop, g_wop);

    const size_t BV = (size_t)B_ * V_;
    const size_t BH = (size_t)B_ * H_;
    float* ht_out = ((size_t)out_size >= BV + 2 * BH) ? (out + BV)      : htbuf;
    float* ct_out = ((size_t)out_size >= BV + 2 * BH) ? (out + BV + BH) : ctbuf;

    dim3 blk(256);
    dim3 g_h(8, 32);

    // Pre-round w_op to tf32: exactly H_*V_ floats, 4/thread, 256 thr/blk = 32000 blocks.
    round_wop<<<ROUND_WOP_BLOCKS, blk>>>(w_op, wop);

    // Gate pre-activations — 4 separate pipelined launches (R6-measured config)
    gemm_tf32<0, 3><<<g_h, blk, SMEM_BYTES>>>(x, w_ip_f, h, w_forget, c, w_forget_c, zf, 1024);
    gemm_tf32<0, 3><<<g_h, blk, SMEM_BYTES>>>(x, w_ip_i, h, w_input,  c, w_input_c,  zi, 1024);
    gemm_tf32<0, 2><<<g_h, blk, SMEM_BYTES>>>(x, w_ip_c, h, w_c_dash, nullptr, nullptr, zc, 1024);
    gemm_tf32<0, 2><<<g_h, blk, SMEM_BYTES>>>(x, w_ip_o, h, w_output, nullptr, nullptr, zo, 1024);

    lstm_ew1<<<(unsigned)(BH / 256), blk>>>(zf, zi, zc, c, ct_out, (int)BH);

    // zo += Ct @ w_output_c
    gemm_tf32<1, 1><<<g_h, blk, SMEM_BYTES>>>(ct_out, w_output_c, nullptr, nullptr, nullptr, nullptr,
                                              zo, 1024);

    lstm_ew2<<<(unsigned)(BH / 256), blk>>>(zo, ct_out, ht_out, htr, (int)BH);

    // Yt = sigmoid(Htr @ Wop_rounded) — conversion-free inner loop, 2 CTAs/SM
    vocab_kernel<<<dim3(250, 32), blk>>>(htr, wop, out, V_);
}